// round 14
// baseline (speedup 1.0000x reference)
#include <cuda_runtime.h>
#include <cuda_fp16.h>
#include <cuda_bf16.h>
#include <cstdint>

#define NNODES 8192
#define NEDGES 262144
#define DIN    512
#define DH     256
#define ALPHA  0.1520f
#define BETA   0.7900f
#define CAPLG  7
#define CAP    128   // padded bin capacity per dst node (mean deg = 32, max ~60)

// ---------------- scratch (device globals; no allocation allowed) ----------
// INVARIANT: g_cur == 0 on entry (zero-init at load; re-zeroed by prop2fin).
__device__ int   g_cur [NNODES];
__device__ float g_dinv[NNODES];
__device__ int   g_esrc[NNODES * CAP];
__device__ __nv_bfloat16 g_Xh [NNODES * DIN];
__device__ __nv_bfloat16 g_Xl [NNODES * DIN];
__device__ __nv_bfloat16 g_W1h[DIN * DH];
__device__ __nv_bfloat16 g_W1l[DIN * DH];
__device__ __half g_Y1h[NNODES * DH];
__device__ float g_Y2  [NNODES * 2];
__device__ float g_ex  [NNODES];
__device__ float g_ey  [NNODES];

// ---------------- scatter edges into padded bins (by dst); counts degree ---
__global__ void scatter_kernel(const int* __restrict__ src, const int* __restrict__ dst) {
    int t = blockIdx.x * blockDim.x + threadIdx.x;   // NEDGES/4 threads
#pragma unroll
    for (int j = 0; j < 4; ++j) {
        int e = t + j * (NEDGES / 4);
        int s = __ldg(&src[e]);
        int d = __ldg(&dst[e]);
        int pos = atomicAdd(&g_cur[d], 1);
        g_esrc[(d << CAPLG) + pos] = s;
    }
}

// ---------------- bf16 split pre-pass (X, W1) + dinv fused -----------------
__device__ __forceinline__ uint32_t pack_hi2(float a, float b) {
    __nv_bfloat16 h0 = __float2bfloat16_rn(a);
    __nv_bfloat16 h1 = __float2bfloat16_rn(b);
    return ((uint32_t)__bfloat16_as_ushort(h1) << 16) | __bfloat16_as_ushort(h0);
}
__device__ __forceinline__ uint32_t pack_lo2(float a, float b) {
    __nv_bfloat16 h0 = __float2bfloat16_rn(a);
    __nv_bfloat16 h1 = __float2bfloat16_rn(b);
    __nv_bfloat16 l0 = __float2bfloat16_rn(a - __bfloat162float(h0));
    __nv_bfloat16 l1 = __float2bfloat16_rn(b - __bfloat162float(h1));
    return ((uint32_t)__bfloat16_as_ushort(l1) << 16) | __bfloat16_as_ushort(l0);
}
__device__ __forceinline__ void split8(float4 v0, float4 v1, uint4* ph, uint4* pl) {
    ph->x = pack_hi2(v0.x, v0.y); ph->y = pack_hi2(v0.z, v0.w);
    ph->z = pack_hi2(v1.x, v1.y); ph->w = pack_hi2(v1.z, v1.w);
    pl->x = pack_lo2(v0.x, v0.y); pl->y = pack_lo2(v0.z, v0.w);
    pl->z = pack_lo2(v1.x, v1.y); pl->w = pack_lo2(v1.z, v1.w);
}

__global__ void split_kernel(const float* __restrict__ X, const float* __restrict__ W1) {
    int i = blockIdx.x * blockDim.x + threadIdx.x;   // NNODES*DIN/16 threads
    const int HALF = NNODES * DIN / 16;
    // two independent 8-float groups per thread (MLP=4 LDG.128)
    float4 v0a = __ldg(&((const float4*)X)[2 * i]);
    float4 v1a = __ldg(&((const float4*)X)[2 * i + 1]);
    float4 v0b = __ldg(&((const float4*)X)[2 * (i + HALF)]);
    float4 v1b = __ldg(&((const float4*)X)[2 * (i + HALF) + 1]);
    uint4 ph, pl;
    split8(v0a, v1a, &ph, &pl);
    ((uint4*)g_Xh)[i] = ph;
    ((uint4*)g_Xl)[i] = pl;
    split8(v0b, v1b, &ph, &pl);
    ((uint4*)g_Xh)[i + HALF] = ph;
    ((uint4*)g_Xl)[i + HALF] = pl;
    if (i < DIN * DH / 8) {
        float4 w0 = __ldg(&((const float4*)W1)[2 * i]);
        float4 w1 = __ldg(&((const float4*)W1)[2 * i + 1]);
        split8(w0, w1, &ph, &pl);
        ((uint4*)g_W1h)[i] = ph;
        ((uint4*)g_W1l)[i] = pl;
    }
    if (i < NNODES) {
        g_dinv[i] = rsqrtf((float)g_cur[i] + 1.0f);
    }
}

// ================= GEMM1 via mma.sync bf16 (3-term split) ==================
#define CHUNK_K     32
#define NCHUNKS     (DIN / CHUNK_K)      // 16
#define STAGE_BYTES 24576
#define NSTAGES     4
#define GEMM_SMEM   (NSTAGES * STAGE_BYTES)

__device__ __forceinline__ uint32_t smem_u32(const void* p) {
    uint32_t a;
    asm("{ .reg .u64 t; cvta.to.shared.u64 t, %1; cvt.u32.u64 %0, t; }" : "=r"(a) : "l"(p));
    return a;
}
__device__ __forceinline__ void cp16(uint32_t dst, const void* src) {
    asm volatile("cp.async.cg.shared.global [%0], [%1], 16;" :: "r"(dst), "l"(src));
}
__device__ __forceinline__ void ldmatrix_x4(uint32_t* r, uint32_t addr) {
    asm volatile("ldmatrix.sync.aligned.m8n8.x4.shared.b16 {%0,%1,%2,%3}, [%4];"
                 : "=r"(r[0]), "=r"(r[1]), "=r"(r[2]), "=r"(r[3]) : "r"(addr));
}
__device__ __forceinline__ void ldmatrix_x2t(uint32_t* r, uint32_t addr) {
    asm volatile("ldmatrix.sync.aligned.m8n8.x2.trans.shared.b16 {%0,%1}, [%2];"
                 : "=r"(r[0]), "=r"(r[1]) : "r"(addr));
}
__device__ __forceinline__ void mma_bf16(float* d, const uint32_t* a, const uint32_t* b) {
    asm volatile(
        "mma.sync.aligned.m16n8k16.row.col.f32.bf16.bf16.f32 "
        "{%0,%1,%2,%3}, {%4,%5,%6,%7}, {%8,%9}, {%0,%1,%2,%3};"
        : "+f"(d[0]), "+f"(d[1]), "+f"(d[2]), "+f"(d[3])
        : "r"(a[0]), "r"(a[1]), "r"(a[2]), "r"(a[3]), "r"(b[0]), "r"(b[1]));
}

__device__ __forceinline__ void gemm_prefetch(uint32_t sb, int tid, int bm, int bn, int k0) {
#pragma unroll
    for (int p = 0; p < 2; ++p) {
        int idx = tid + p * 256;
        int row = idx >> 2, c16 = idx & 3;
        uint32_t off = (uint32_t)(row * 64 + c16 * 16);
        off ^= (uint32_t)(row & 3) << 4;
        cp16(sb + off,        g_Xh + (size_t)(bm + row) * DIN + k0 + c16 * 8);
        cp16(sb + 8192 + off, g_Xl + (size_t)(bm + row) * DIN + k0 + c16 * 8);
    }
    {
        int row = tid >> 3, c16 = tid & 7;
        uint32_t off = (uint32_t)(row * 128 + c16 * 16);
        off ^= (uint32_t)(row & 7) << 4;
        cp16(sb + 16384 + off, g_W1h + (size_t)(k0 + row) * DH + bn + c16 * 8);
        cp16(sb + 20480 + off, g_W1l + (size_t)(k0 + row) * DH + bn + c16 * 8);
    }
}

__global__ __launch_bounds__(256) void gemm1_mma_kernel() {
    extern __shared__ __align__(1024) char sm[];
    const uint32_t sbase = smem_u32(sm);
    const int tid = threadIdx.x;
    const int wid = tid >> 5, lane = tid & 31;
    const int bm = blockIdx.y * 128;
    const int bn = blockIdx.x * 64;
    const int wm0 = (wid & 3) * 32;
    const int wn0 = (wid >> 2) * 32;

    float d[2][4][4];
#pragma unroll
    for (int mt = 0; mt < 2; ++mt)
#pragma unroll
        for (int nt = 0; nt < 4; ++nt)
#pragma unroll
            for (int u = 0; u < 4; ++u) d[mt][nt][u] = 0.f;

#pragma unroll
    for (int c = 0; c < NSTAGES - 1; ++c) {
        gemm_prefetch(sbase + (uint32_t)c * STAGE_BYTES, tid, bm, bn, c * CHUNK_K);
        asm volatile("cp.async.commit_group;");
    }

    for (int ch = 0; ch < NCHUNKS; ++ch) {
        asm volatile("cp.async.wait_group %0;" :: "n"(NSTAGES - 2));
        __syncthreads();
        const uint32_t stb = sbase + (uint32_t)(ch & (NSTAGES - 1)) * STAGE_BYTES;

#pragma unroll
        for (int ks = 0; ks < 2; ++ks) {
            const int kk = ks * 16;
            uint32_t ah[2][4], al[2][4], bh[4][2], bl[4][2];
#pragma unroll
            for (int mt = 0; mt < 2; ++mt) {
                int row = wm0 + mt * 16 + (lane & 15);
                uint32_t off = (uint32_t)(row * 64 + kk * 2 + ((lane >> 4) << 4));
                off ^= (uint32_t)(row & 3) << 4;
                ldmatrix_x4(ah[mt], stb + off);
                ldmatrix_x4(al[mt], stb + 8192 + off);
            }
#pragma unroll
            for (int nt = 0; nt < 4; ++nt) {
                int row = kk + (lane & 15);
                uint32_t off = (uint32_t)(row * 128 + (wn0 + nt * 8) * 2);
                off ^= (uint32_t)(row & 7) << 4;
                ldmatrix_x2t(bh[nt], stb + 16384 + off);
                ldmatrix_x2t(bl[nt], stb + 20480 + off);
            }
#pragma unroll
            for (int mt = 0; mt < 2; ++mt)
#pragma unroll
                for (int nt = 0; nt < 4; ++nt) {
                    mma_bf16(d[mt][nt], ah[mt], bh[nt]);
                    mma_bf16(d[mt][nt], ah[mt], bl[nt]);
                    mma_bf16(d[mt][nt], al[mt], bh[nt]);
                }
        }

        if (ch + NSTAGES - 1 < NCHUNKS) {
            gemm_prefetch(sbase + (uint32_t)((ch + NSTAGES - 1) & (NSTAGES - 1)) * STAGE_BYTES,
                          tid, bm, bn, (ch + NSTAGES - 1) * CHUNK_K);
        }
        asm volatile("cp.async.commit_group;");
    }

    const int group = lane >> 2, tig = lane & 3;
#pragma unroll
    for (int mt = 0; mt < 2; ++mt) {
#pragma unroll
        for (int nt = 0; nt < 4; ++nt) {
            int row = bm + wm0 + mt * 16 + group;
            int col = bn + wn0 + nt * 8 + tig * 2;
            __half2 h01 = __floats2half2_rn(d[mt][nt][0], d[mt][nt][1]);
            __half2 h23 = __floats2half2_rn(d[mt][nt][2], d[mt][nt][3]);
            *(__half2*)&g_Y1h[(size_t)row * DH + col] = h01;
            *(__half2*)&g_Y1h[(size_t)(row + 8) * DH + col] = h23;
        }
    }
}

// ------ fused prop1 + self-loop + bias + relu + @W2 (warp per dst node) ----
__device__ __forceinline__ void acc8_fp16(uint4 v, float n, float4* a0, float4* a1) {
    float2 f0 = __half22float2(*(__half2*)&v.x);
    float2 f1 = __half22float2(*(__half2*)&v.y);
    float2 f2 = __half22float2(*(__half2*)&v.z);
    float2 f3 = __half22float2(*(__half2*)&v.w);
    a0->x = fmaf(n, f0.x, a0->x); a0->y = fmaf(n, f0.y, a0->y);
    a0->z = fmaf(n, f1.x, a0->z); a0->w = fmaf(n, f1.y, a0->w);
    a1->x = fmaf(n, f2.x, a1->x); a1->y = fmaf(n, f2.y, a1->y);
    a1->z = fmaf(n, f3.x, a1->z); a1->w = fmaf(n, f3.y, a1->w);
}

__global__ __launch_bounds__(256) void prop1node2_kernel(const float* __restrict__ b1,
                                                         const float* __restrict__ W2) {
    const int node = (blockIdx.x * blockDim.x + threadIdx.x) >> 5;
    const int lane = threadIdx.x & 31;
    if (node >= NNODES) return;
    const int e0 = node << CAPLG;
    const int cnt = g_cur[node];
    const float di = g_dinv[node];

    float4 a0 = make_float4(0.f, 0.f, 0.f, 0.f);
    float4 a1 = make_float4(0.f, 0.f, 0.f, 0.f);

    int e = 0;
    // 4-edge unroll: 4 independent gather chains in flight per lane
    for (; e + 4 <= cnt; e += 4) {
        int s0 = __ldg(&g_esrc[e0 + e]);
        int s1 = __ldg(&g_esrc[e0 + e + 1]);
        int s2 = __ldg(&g_esrc[e0 + e + 2]);
        int s3 = __ldg(&g_esrc[e0 + e + 3]);
        float n0 = __ldg(&g_dinv[s0]) * di;
        float n1 = __ldg(&g_dinv[s1]) * di;
        float n2 = __ldg(&g_dinv[s2]) * di;
        float n3 = __ldg(&g_dinv[s3]) * di;
        uint4 v0 = __ldg(&((const uint4*)(g_Y1h + (size_t)s0 * DH))[lane]);
        uint4 v1 = __ldg(&((const uint4*)(g_Y1h + (size_t)s1 * DH))[lane]);
        uint4 v2 = __ldg(&((const uint4*)(g_Y1h + (size_t)s2 * DH))[lane]);
        uint4 v3 = __ldg(&((const uint4*)(g_Y1h + (size_t)s3 * DH))[lane]);
        acc8_fp16(v0, n0, &a0, &a1);
        acc8_fp16(v1, n1, &a0, &a1);
        acc8_fp16(v2, n2, &a0, &a1);
        acc8_fp16(v3, n3, &a0, &a1);
    }
    for (; e < cnt; ++e) {
        int s = __ldg(&g_esrc[e0 + e]);
        float n = __ldg(&g_dinv[s]) * di;
        uint4 v = __ldg(&((const uint4*)(g_Y1h + (size_t)s * DH))[lane]);
        acc8_fp16(v, n, &a0, &a1);
    }

    {   // self loop
        uint4 vS = __ldg(&((const uint4*)(g_Y1h + (size_t)node * DH))[lane]);
        acc8_fp16(vS, di * di, &a0, &a1);
    }

    const int fi = 2 * lane;
    float4 b0v = __ldg(&((const float4*)b1)[fi]);
    float4 b1v = __ldg(&((const float4*)b1)[fi + 1]);
    float h[8];
    h[0] = fmaxf(a0.x + b0v.x, 0.f); h[1] = fmaxf(a0.y + b0v.y, 0.f);
    h[2] = fmaxf(a0.z + b0v.z, 0.f); h[3] = fmaxf(a0.w + b0v.w, 0.f);
    h[4] = fmaxf(a1.x + b1v.x, 0.f); h[5] = fmaxf(a1.y + b1v.y, 0.f);
    h[6] = fmaxf(a1.z + b1v.z, 0.f); h[7] = fmaxf(a1.w + b1v.w, 0.f);
    float p0 = 0.f, p1 = 0.f;
#pragma unroll
    for (int j = 0; j < 8; ++j) {
        float2 w = __ldg(&((const float2*)W2)[lane * 8 + j]);
        p0 = fmaf(h[j], w.x, p0);
        p1 = fmaf(h[j], w.y, p1);
    }
#pragma unroll
    for (int off = 16; off > 0; off >>= 1) {
        p0 += __shfl_down_sync(0xffffffffu, p0, off);
        p1 += __shfl_down_sync(0xffffffffu, p1, off);
    }
    if (lane == 0) {
        g_Y2[node * 2 + 0] = p0;
        g_Y2[node * 2 + 1] = p1;
    }
}

// ------ fused prop2 + finalize (warp per dst node); re-zeroes g_cur --------
__global__ __launch_bounds__(256) void prop2fin_kernel(const float* __restrict__ b2,
                                                       float* __restrict__ out) {
    const int node = (blockIdx.x * blockDim.x + threadIdx.x) >> 5;
    const int lane = threadIdx.x & 31;
    if (node >= NNODES) return;
    const int e0 = node << CAPLG;
    const int cnt = g_cur[node];
    const float di = g_dinv[node];
    float sx = 0.f, sy = 0.f;
    for (int e = lane; e < cnt; e += 32) {
        int s = __ldg(&g_esrc[e0 + e]);
        float n = __ldg(&g_dinv[s]) * di;
        float2 y = __ldg(&((const float2*)g_Y2)[s]);
        sx = fmaf(n, y.x, sx);
        sy = fmaf(n, y.y, sy);
    }
#pragma unroll
    for (int off = 16; off > 0; off >>= 1) {
        sx += __shfl_down_sync(0xffffffffu, sx, off);
        sy += __shfl_down_sync(0xffffffffu, sy, off);
    }
    if (lane == 0) {
        float di2 = di * di;
        float2 y = __ldg(&((const float2*)g_Y2)[node]);
        float ex = sx + y.x * di2 + b2[0];
        float ey = sy + y.y * di2 + b2[1];
        g_ex[node] = ex;
        g_ey[node] = ey;
        out[2 * node + 0] = ex;
        out[2 * node + 1] = ey;
        g_cur[node] = 0;
    }
}

// ---------------- q: symmetric upper-triangular 64x64 tiles ----------------
__device__ __forceinline__ float qval(float dx, float dy) {
    float d2 = fmaf(dx, dx, dy * dy);
    float pw = __powf(d2, BETA);
    float q  = __fdividef(1.0f, fmaf(ALPHA, pw, 1.0f));
    return d2 > 0.0f ? q : 1.0f;
}

__global__ __launch_bounds__(256) void q_kernel(float* __restrict__ qout) {
    __shared__ float qs[64][65];
    int b = blockIdx.x;
    int r = (int)((257.0f - sqrtf(66049.0f - 8.0f * (float)b)) * 0.5f);
    while ((r + 1) * 128 - ((r + 1) * r) / 2 <= b) ++r;
    while (r * 128 - (r * (r - 1)) / 2 > b) --r;
    int S = r * 128 - (r * (r - 1)) / 2;
    int bi = r;
    int bj = r + (b - S);
    int ty = threadIdx.x >> 4, tx = threadIdx.x & 15;
    int r0 = ty * 4, c0 = tx * 4;
    bool diag = (bi == bj);

    float4 xj = *(const float4*)&g_ex[bj * 64 + c0];
    float4 yj = *(const float4*)&g_ey[bj * 64 + c0];
#pragma unroll
    for (int u = 0; u < 4; ++u) {
        float xi = g_ex[bi * 64 + r0 + u];
        float yi = g_ey[bi * 64 + r0 + u];
        float4 v;
        v.x = qval(xi - xj.x, yi - yj.x);
        v.y = qval(xi - xj.y, yi - yj.y);
        v.z = qval(xi - xj.z, yi - yj.z);
        v.w = qval(xi - xj.w, yi - yj.w);
        __stcs((float4*)&qout[(size_t)(bi * 64 + r0 + u) * NNODES + bj * 64 + c0], v);
        if (!diag) {
            qs[r0 + u][c0 + 0] = v.x;
            qs[r0 + u][c0 + 1] = v.y;
            qs[r0 + u][c0 + 2] = v.z;
            qs[r0 + u][c0 + 3] = v.w;
        }
    }
    if (!diag) {
        __syncthreads();
#pragma unroll
        for (int u = 0; u < 4; ++u) {
            float4 v;
            v.x = qs[c0 + 0][r0 + u];
            v.y = qs[c0 + 1][r0 + u];
            v.z = qs[c0 + 2][r0 + u];
            v.w = qs[c0 + 3][r0 + u];
            __stcs((float4*)&qout[(size_t)(bj * 64 + r0 + u) * NNODES + bi * 64 + c0], v);
        }
    }
}

// ---------------------------------------------------------------------------
extern "C" void kernel_launch(void* const* d_in, const int* in_sizes, int n_in,
                              void* d_out, int out_size) {
    const float* X  = (const float*)d_in[0];
    const int*   ei = (const int*)  d_in[1];
    const float* W1 = (const float*)d_in[2];
    const float* b1 = (const float*)d_in[3];
    const float* W2 = (const float*)d_in[4];
    const float* b2 = (const float*)d_in[5];
    float* out = (float*)d_out;
    (void)in_sizes; (void)n_in; (void)out_size;

    const int* src = ei;
    const int* dst = ei + NEDGES;

    cudaFuncSetAttribute(gemm1_mma_kernel,
                         cudaFuncAttributeMaxDynamicSharedMemorySize, GEMM_SMEM);

    scatter_kernel<<<NEDGES / 4 / 256, 256>>>(src, dst);
    split_kernel<<<NNODES * DIN / 16 / 256, 256>>>(X, W1);   // + dinv fused
    gemm1_mma_kernel<<<dim3(DH / 64, NNODES / 128), 256, GEMM_SMEM>>>();
    prop1node2_kernel<<<NNODES * 32 / 256, 256>>>(b1, W2);
    prop2fin_kernel<<<NNODES * 32 / 256, 256>>>(b2, out);    // re-zeroes g_cur
    q_kernel<<<128 * 129 / 2, 256>>>(out + NNODES * 2);
}

// round 15
// speedup vs baseline: 1.0105x; 1.0105x over previous
#include <cuda_runtime.h>
#include <cuda_fp16.h>
#include <cuda_bf16.h>
#include <cstdint>

#define NNODES 8192
#define NEDGES 262144
#define DIN    512
#define DH     256
#define ALPHA  0.1520f
#define BETA   0.7900f
#define CAPLG  7
#define CAP    128   // padded bin capacity per dst node (mean deg = 32, max ~60)

// ---------------- scratch (device globals; no allocation allowed) ----------
// INVARIANT: g_cur == 0 on entry (zero-init at load; re-zeroed by prop2fin).
__device__ int   g_cur [NNODES];
__device__ float g_dinv[NNODES];
__device__ int   g_esrc[NNODES * CAP];
__device__ __nv_bfloat16 g_Xh [NNODES * DIN];
__device__ __nv_bfloat16 g_Xl [NNODES * DIN];
__device__ __nv_bfloat16 g_W1h[DIN * DH];
__device__ __nv_bfloat16 g_W1l[DIN * DH];
__device__ __half g_Y1h[NNODES * DH];
__device__ float g_Y2  [NNODES * 2];
__device__ float g_ex  [NNODES];
__device__ float g_ey  [NNODES];

// ---------------- scatter edges into padded bins (by dst); counts degree ---
__global__ void scatter_kernel(const int* __restrict__ src, const int* __restrict__ dst) {
    int t = blockIdx.x * blockDim.x + threadIdx.x;   // NEDGES/4 threads
#pragma unroll
    for (int j = 0; j < 4; ++j) {
        int e = t + j * (NEDGES / 4);
        int s = __ldg(&src[e]);
        int d = __ldg(&dst[e]);
        int pos = atomicAdd(&g_cur[d], 1);
        g_esrc[(d << CAPLG) + pos] = s;
    }
}

// ---------------- bf16 split pre-pass (X, W1) + dinv fused -----------------
__device__ __forceinline__ uint32_t pack_hi2(float a, float b) {
    __nv_bfloat16 h0 = __float2bfloat16_rn(a);
    __nv_bfloat16 h1 = __float2bfloat16_rn(b);
    return ((uint32_t)__bfloat16_as_ushort(h1) << 16) | __bfloat16_as_ushort(h0);
}
__device__ __forceinline__ uint32_t pack_lo2(float a, float b) {
    __nv_bfloat16 h0 = __float2bfloat16_rn(a);
    __nv_bfloat16 h1 = __float2bfloat16_rn(b);
    __nv_bfloat16 l0 = __float2bfloat16_rn(a - __bfloat162float(h0));
    __nv_bfloat16 l1 = __float2bfloat16_rn(b - __bfloat162float(h1));
    return ((uint32_t)__bfloat16_as_ushort(l1) << 16) | __bfloat16_as_ushort(l0);
}
__device__ __forceinline__ void split8(float4 v0, float4 v1, uint4* ph, uint4* pl) {
    ph->x = pack_hi2(v0.x, v0.y); ph->y = pack_hi2(v0.z, v0.w);
    ph->z = pack_hi2(v1.x, v1.y); ph->w = pack_hi2(v1.z, v1.w);
    pl->x = pack_lo2(v0.x, v0.y); pl->y = pack_lo2(v0.z, v0.w);
    pl->z = pack_lo2(v1.x, v1.y); pl->w = pack_lo2(v1.z, v1.w);
}

__global__ void split_kernel(const float* __restrict__ X, const float* __restrict__ W1) {
    int i = blockIdx.x * blockDim.x + threadIdx.x;   // NNODES*DIN/16 threads
    const int HALF = NNODES * DIN / 16;
    float4 v0a = __ldg(&((const float4*)X)[2 * i]);
    float4 v1a = __ldg(&((const float4*)X)[2 * i + 1]);
    float4 v0b = __ldg(&((const float4*)X)[2 * (i + HALF)]);
    float4 v1b = __ldg(&((const float4*)X)[2 * (i + HALF) + 1]);
    uint4 ph, pl;
    split8(v0a, v1a, &ph, &pl);
    ((uint4*)g_Xh)[i] = ph;
    ((uint4*)g_Xl)[i] = pl;
    split8(v0b, v1b, &ph, &pl);
    ((uint4*)g_Xh)[i + HALF] = ph;
    ((uint4*)g_Xl)[i + HALF] = pl;
    if (i < DIN * DH / 8) {
        float4 w0 = __ldg(&((const float4*)W1)[2 * i]);
        float4 w1 = __ldg(&((const float4*)W1)[2 * i + 1]);
        split8(w0, w1, &ph, &pl);
        ((uint4*)g_W1h)[i] = ph;
        ((uint4*)g_W1l)[i] = pl;
    }
    if (i < NNODES) {
        g_dinv[i] = rsqrtf((float)g_cur[i] + 1.0f);
    }
}

// ================= GEMM1 via mma.sync bf16 (3-term split) ==================
#define CHUNK_K     32
#define NCHUNKS     (DIN / CHUNK_K)      // 16
#define STAGE_BYTES 24576
#define NSTAGES     4
#define GEMM_SMEM   (NSTAGES * STAGE_BYTES)

__device__ __forceinline__ uint32_t smem_u32(const void* p) {
    uint32_t a;
    asm("{ .reg .u64 t; cvta.to.shared.u64 t, %1; cvt.u32.u64 %0, t; }" : "=r"(a) : "l"(p));
    return a;
}
__device__ __forceinline__ void cp16(uint32_t dst, const void* src) {
    asm volatile("cp.async.cg.shared.global [%0], [%1], 16;" :: "r"(dst), "l"(src));
}
__device__ __forceinline__ void ldmatrix_x4(uint32_t* r, uint32_t addr) {
    asm volatile("ldmatrix.sync.aligned.m8n8.x4.shared.b16 {%0,%1,%2,%3}, [%4];"
                 : "=r"(r[0]), "=r"(r[1]), "=r"(r[2]), "=r"(r[3]) : "r"(addr));
}
__device__ __forceinline__ void ldmatrix_x2t(uint32_t* r, uint32_t addr) {
    asm volatile("ldmatrix.sync.aligned.m8n8.x2.trans.shared.b16 {%0,%1}, [%2];"
                 : "=r"(r[0]), "=r"(r[1]) : "r"(addr));
}
__device__ __forceinline__ void mma_bf16(float* d, const uint32_t* a, const uint32_t* b) {
    asm volatile(
        "mma.sync.aligned.m16n8k16.row.col.f32.bf16.bf16.f32 "
        "{%0,%1,%2,%3}, {%4,%5,%6,%7}, {%8,%9}, {%0,%1,%2,%3};"
        : "+f"(d[0]), "+f"(d[1]), "+f"(d[2]), "+f"(d[3])
        : "r"(a[0]), "r"(a[1]), "r"(a[2]), "r"(a[3]), "r"(b[0]), "r"(b[1]));
}

__device__ __forceinline__ void gemm_prefetch(uint32_t sb, int tid, int bm, int bn, int k0) {
#pragma unroll
    for (int p = 0; p < 2; ++p) {
        int idx = tid + p * 256;
        int row = idx >> 2, c16 = idx & 3;
        uint32_t off = (uint32_t)(row * 64 + c16 * 16);
        off ^= (uint32_t)(row & 3) << 4;
        cp16(sb + off,        g_Xh + (size_t)(bm + row) * DIN + k0 + c16 * 8);
        cp16(sb + 8192 + off, g_Xl + (size_t)(bm + row) * DIN + k0 + c16 * 8);
    }
    {
        int row = tid >> 3, c16 = tid & 7;
        uint32_t off = (uint32_t)(row * 128 + c16 * 16);
        off ^= (uint32_t)(row & 7) << 4;
        cp16(sb + 16384 + off, g_W1h + (size_t)(k0 + row) * DH + bn + c16 * 8);
        cp16(sb + 20480 + off, g_W1l + (size_t)(k0 + row) * DH + bn + c16 * 8);
    }
}

__global__ __launch_bounds__(256) void gemm1_mma_kernel() {
    extern __shared__ __align__(1024) char sm[];
    const uint32_t sbase = smem_u32(sm);
    const int tid = threadIdx.x;
    const int wid = tid >> 5, lane = tid & 31;
    const int bm = blockIdx.y * 128;
    const int bn = blockIdx.x * 64;
    const int wm0 = (wid & 3) * 32;
    const int wn0 = (wid >> 2) * 32;

    float d[2][4][4];
#pragma unroll
    for (int mt = 0; mt < 2; ++mt)
#pragma unroll
        for (int nt = 0; nt < 4; ++nt)
#pragma unroll
            for (int u = 0; u < 4; ++u) d[mt][nt][u] = 0.f;

#pragma unroll
    for (int c = 0; c < NSTAGES - 1; ++c) {
        gemm_prefetch(sbase + (uint32_t)c * STAGE_BYTES, tid, bm, bn, c * CHUNK_K);
        asm volatile("cp.async.commit_group;");
    }

    for (int ch = 0; ch < NCHUNKS; ++ch) {
        asm volatile("cp.async.wait_group %0;" :: "n"(NSTAGES - 2));
        __syncthreads();
        const uint32_t stb = sbase + (uint32_t)(ch & (NSTAGES - 1)) * STAGE_BYTES;

#pragma unroll
        for (int ks = 0; ks < 2; ++ks) {
            const int kk = ks * 16;
            uint32_t ah[2][4], al[2][4], bh[4][2], bl[4][2];
#pragma unroll
            for (int mt = 0; mt < 2; ++mt) {
                int row = wm0 + mt * 16 + (lane & 15);
                uint32_t off = (uint32_t)(row * 64 + kk * 2 + ((lane >> 4) << 4));
                off ^= (uint32_t)(row & 3) << 4;
                ldmatrix_x4(ah[mt], stb + off);
                ldmatrix_x4(al[mt], stb + 8192 + off);
            }
#pragma unroll
            for (int nt = 0; nt < 4; ++nt) {
                int row = kk + (lane & 15);
                uint32_t off = (uint32_t)(row * 128 + (wn0 + nt * 8) * 2);
                off ^= (uint32_t)(row & 7) << 4;
                ldmatrix_x2t(bh[nt], stb + 16384 + off);
                ldmatrix_x2t(bl[nt], stb + 20480 + off);
            }
#pragma unroll
            for (int mt = 0; mt < 2; ++mt)
#pragma unroll
                for (int nt = 0; nt < 4; ++nt) {
                    mma_bf16(d[mt][nt], ah[mt], bh[nt]);
                    mma_bf16(d[mt][nt], ah[mt], bl[nt]);
                    mma_bf16(d[mt][nt], al[mt], bh[nt]);
                }
        }

        if (ch + NSTAGES - 1 < NCHUNKS) {
            gemm_prefetch(sbase + (uint32_t)((ch + NSTAGES - 1) & (NSTAGES - 1)) * STAGE_BYTES,
                          tid, bm, bn, (ch + NSTAGES - 1) * CHUNK_K);
        }
        asm volatile("cp.async.commit_group;");
    }

    const int group = lane >> 2, tig = lane & 3;
#pragma unroll
    for (int mt = 0; mt < 2; ++mt) {
#pragma unroll
        for (int nt = 0; nt < 4; ++nt) {
            int row = bm + wm0 + mt * 16 + group;
            int col = bn + wn0 + nt * 8 + tig * 2;
            __half2 h01 = __floats2half2_rn(d[mt][nt][0], d[mt][nt][1]);
            __half2 h23 = __floats2half2_rn(d[mt][nt][2], d[mt][nt][3]);
            *(__half2*)&g_Y1h[(size_t)row * DH + col] = h01;
            *(__half2*)&g_Y1h[(size_t)(row + 8) * DH + col] = h23;
        }
    }
}

// ------ fused prop1 + self-loop + bias + relu + @W2 -------------------------
// TWO warps per node: each walks the even/odd half of the edge list (stride 2,
// 2-deep pipeline); partials merge via smem; half 0 finishes bias/relu/W2.
__device__ __forceinline__ void acc8_fp16(uint4 v, float n, float4* a0, float4* a1) {
    float2 f0 = __half22float2(*(__half2*)&v.x);
    float2 f1 = __half22float2(*(__half2*)&v.y);
    float2 f2 = __half22float2(*(__half2*)&v.z);
    float2 f3 = __half22float2(*(__half2*)&v.w);
    a0->x = fmaf(n, f0.x, a0->x); a0->y = fmaf(n, f0.y, a0->y);
    a0->z = fmaf(n, f1.x, a0->z); a0->w = fmaf(n, f1.y, a0->w);
    a1->x = fmaf(n, f2.x, a1->x); a1->y = fmaf(n, f2.y, a1->y);
    a1->z = fmaf(n, f3.x, a1->z); a1->w = fmaf(n, f3.y, a1->w);
}

__global__ __launch_bounds__(256) void prop1node2_kernel(const float* __restrict__ b1,
                                                         const float* __restrict__ W2) {
    __shared__ float4 s0[4][33], s1[4][33];   // half-1 partials (pad kills conflicts)
    const int wid = threadIdx.x >> 5;
    const int lane = threadIdx.x & 31;
    const int nl = wid >> 1;                  // node slot in block: 0..3
    const int half = wid & 1;
    const int node = blockIdx.x * 4 + nl;
    const int e0 = node << CAPLG;
    const int cnt = g_cur[node];
    const float di = g_dinv[node];

    float4 a0 = make_float4(0.f, 0.f, 0.f, 0.f);
    float4 a1 = make_float4(0.f, 0.f, 0.f, 0.f);

    int e = half;
    // two independent stride-2 chains in flight (e, e+2); step 4
    for (; e + 2 < cnt; e += 4) {
        int sA = __ldg(&g_esrc[e0 + e]);
        int sB = __ldg(&g_esrc[e0 + e + 2]);
        float nA = __ldg(&g_dinv[sA]) * di;
        float nB = __ldg(&g_dinv[sB]) * di;
        uint4 vA = __ldg(&((const uint4*)(g_Y1h + (size_t)sA * DH))[lane]);
        uint4 vB = __ldg(&((const uint4*)(g_Y1h + (size_t)sB * DH))[lane]);
        acc8_fp16(vA, nA, &a0, &a1);
        acc8_fp16(vB, nB, &a0, &a1);
    }
    if (e < cnt) {
        int sA = __ldg(&g_esrc[e0 + e]);
        float nA = __ldg(&g_dinv[sA]) * di;
        uint4 vA = __ldg(&((const uint4*)(g_Y1h + (size_t)sA * DH))[lane]);
        acc8_fp16(vA, nA, &a0, &a1);
    }

    if (half == 1) {
        s0[nl][lane] = a0;
        s1[nl][lane] = a1;
    }
    __syncthreads();
    if (half == 1) return;

    {   // merge halves
        float4 t0 = s0[nl][lane], t1 = s1[nl][lane];
        a0.x += t0.x; a0.y += t0.y; a0.z += t0.z; a0.w += t0.w;
        a1.x += t1.x; a1.y += t1.y; a1.z += t1.z; a1.w += t1.w;
    }
    {   // self loop
        uint4 vS = __ldg(&((const uint4*)(g_Y1h + (size_t)node * DH))[lane]);
        acc8_fp16(vS, di * di, &a0, &a1);
    }

    const int fi = 2 * lane;
    float4 b0v = __ldg(&((const float4*)b1)[fi]);
    float4 b1v = __ldg(&((const float4*)b1)[fi + 1]);
    float h[8];
    h[0] = fmaxf(a0.x + b0v.x, 0.f); h[1] = fmaxf(a0.y + b0v.y, 0.f);
    h[2] = fmaxf(a0.z + b0v.z, 0.f); h[3] = fmaxf(a0.w + b0v.w, 0.f);
    h[4] = fmaxf(a1.x + b1v.x, 0.f); h[5] = fmaxf(a1.y + b1v.y, 0.f);
    h[6] = fmaxf(a1.z + b1v.z, 0.f); h[7] = fmaxf(a1.w + b1v.w, 0.f);
    float p0 = 0.f, p1 = 0.f;
#pragma unroll
    for (int j = 0; j < 8; ++j) {
        float2 w = __ldg(&((const float2*)W2)[lane * 8 + j]);
        p0 = fmaf(h[j], w.x, p0);
        p1 = fmaf(h[j], w.y, p1);
    }
#pragma unroll
    for (int off = 16; off > 0; off >>= 1) {
        p0 += __shfl_down_sync(0xffffffffu, p0, off);
        p1 += __shfl_down_sync(0xffffffffu, p1, off);
    }
    if (lane == 0) {
        g_Y2[node * 2 + 0] = p0;
        g_Y2[node * 2 + 1] = p1;
    }
}

// ------ fused prop2 + finalize (warp per dst node); re-zeroes g_cur --------
__global__ __launch_bounds__(256) void prop2fin_kernel(const float* __restrict__ b2,
                                                       float* __restrict__ out) {
    const int node = (blockIdx.x * blockDim.x + threadIdx.x) >> 5;
    const int lane = threadIdx.x & 31;
    if (node >= NNODES) return;
    const int e0 = node << CAPLG;
    const int cnt = g_cur[node];
    const float di = g_dinv[node];
    float sx = 0.f, sy = 0.f;
    for (int e = lane; e < cnt; e += 32) {
        int s = __ldg(&g_esrc[e0 + e]);
        float n = __ldg(&g_dinv[s]) * di;
        float2 y = __ldg(&((const float2*)g_Y2)[s]);
        sx = fmaf(n, y.x, sx);
        sy = fmaf(n, y.y, sy);
    }
#pragma unroll
    for (int off = 16; off > 0; off >>= 1) {
        sx += __shfl_down_sync(0xffffffffu, sx, off);
        sy += __shfl_down_sync(0xffffffffu, sy, off);
    }
    if (lane == 0) {
        float di2 = di * di;
        float2 y = __ldg(&((const float2*)g_Y2)[node]);
        float ex = sx + y.x * di2 + b2[0];
        float ey = sy + y.y * di2 + b2[1];
        g_ex[node] = ex;
        g_ey[node] = ey;
        out[2 * node + 0] = ex;
        out[2 * node + 1] = ey;
        g_cur[node] = 0;
    }
}

// ---------------- q: symmetric upper-triangular 64x64 tiles ----------------
__device__ __forceinline__ float qval(float dx, float dy) {
    float d2 = fmaf(dx, dx, dy * dy);
    float pw = __powf(d2, BETA);
    float q  = __fdividef(1.0f, fmaf(ALPHA, pw, 1.0f));
    return d2 > 0.0f ? q : 1.0f;
}

__global__ __launch_bounds__(256) void q_kernel(float* __restrict__ qout) {
    __shared__ float qs[64][65];
    int b = blockIdx.x;
    int r = (int)((257.0f - sqrtf(66049.0f - 8.0f * (float)b)) * 0.5f);
    while ((r + 1) * 128 - ((r + 1) * r) / 2 <= b) ++r;
    while (r * 128 - (r * (r - 1)) / 2 > b) --r;
    int S = r * 128 - (r * (r - 1)) / 2;
    int bi = r;
    int bj = r + (b - S);
    int ty = threadIdx.x >> 4, tx = threadIdx.x & 15;
    int r0 = ty * 4, c0 = tx * 4;
    bool diag = (bi == bj);

    float4 xj = *(const float4*)&g_ex[bj * 64 + c0];
    float4 yj = *(const float4*)&g_ey[bj * 64 + c0];
#pragma unroll
    for (int u = 0; u < 4; ++u) {
        float xi = g_ex[bi * 64 + r0 + u];
        float yi = g_ey[bi * 64 + r0 + u];
        float4 v;
        v.x = qval(xi - xj.x, yi - yj.x);
        v.y = qval(xi - xj.y, yi - yj.y);
        v.z = qval(xi - xj.z, yi - yj.z);
        v.w = qval(xi - xj.w, yi - yj.w);
        __stcs((float4*)&qout[(size_t)(bi * 64 + r0 + u) * NNODES + bj * 64 + c0], v);
        if (!diag) {
            qs[r0 + u][c0 + 0] = v.x;
            qs[r0 + u][c0 + 1] = v.y;
            qs[r0 + u][c0 + 2] = v.z;
            qs[r0 + u][c0 + 3] = v.w;
        }
    }
    if (!diag) {
        __syncthreads();
#pragma unroll
        for (int u = 0; u < 4; ++u) {
            float4 v;
            v.x = qs[c0 + 0][r0 + u];
            v.y = qs[c0 + 1][r0 + u];
            v.z = qs[c0 + 2][r0 + u];
            v.w = qs[c0 + 3][r0 + u];
            __stcs((float4*)&qout[(size_t)(bj * 64 + r0 + u) * NNODES + bi * 64 + c0], v);
        }
    }
}

// ---------------------------------------------------------------------------
extern "C" void kernel_launch(void* const* d_in, const int* in_sizes, int n_in,
                              void* d_out, int out_size) {
    const float* X  = (const float*)d_in[0];
    const int*   ei = (const int*)  d_in[1];
    const float* W1 = (const float*)d_in[2];
    const float* b1 = (const float*)d_in[3];
    const float* W2 = (const float*)d_in[4];
    const float* b2 = (const float*)d_in[5];
    float* out = (float*)d_out;
    (void)in_sizes; (void)n_in; (void)out_size;

    const int* src = ei;
    const int* dst = ei + NEDGES;

    cudaFuncSetAttribute(gemm1_mma_kernel,
                         cudaFuncAttributeMaxDynamicSharedMemorySize, GEMM_SMEM);

    scatter_kernel<<<NEDGES / 4 / 256, 256>>>(src, dst);
    split_kernel<<<NNODES * DIN / 16 / 256, 256>>>(X, W1);   // + dinv fused
    gemm1_mma_kernel<<<dim3(DH / 64, NNODES / 128), 256, GEMM_SMEM>>>();
    prop1node2_kernel<<<NNODES / 4, 256>>>(b1, W2);          // 2 warps per node
    prop2fin_kernel<<<NNODES * 32 / 256, 256>>>(b2, out);    // re-zeroes g_cur
    q_kernel<<<128 * 129 / 2, 256>>>(out + NNODES * 2);
}